// round 9
// baseline (speedup 1.0000x reference)
#include <cuda_runtime.h>

#define NDIM 65
#define ND2  4225
#define NV   274625
#define NVB  1073            /* 256-vertex blocks                  */
#define NC   262144          /* 64^3 cubes                         */
#define CPB  128             /* cubes per kEmit face block         */
#define NFB  2048            /* kEmit face blocks / g_tblk entries */
#define NCB  1024            /* kCount cube blocks (256 cubes)     */
#define NBLKC (NVB + NCB)    /* kCount grid                        */
#define NBLKE (NVB + NFB)    /* kEmit grid                         */

// -------- scratch (device globals; no allocations allowed) --------
__device__ unsigned int       g_pkl[NV];      // (block-local excl << 7) | mask
__device__ int                g_vblk[NVB+1];  // block totals -> scanned bases (+M)
__device__ unsigned char      g_occ8[NC];     // per-cube 8-bit occupancy
__device__ unsigned long long g_tblk[NFB];    // lo32=c1 base, hi32=c2 base
__device__ int                g_M;
__device__ int                g_F1;
__device__ unsigned int       g_done = 0;     // tail-block ticket (self-resetting)

__device__ const signed char d_tri[96] = {
  -1,-1,-1,-1,-1,-1,  1,0,2,-1,-1,-1,  4,0,3,-1,-1,-1,  1,4,2,1,3,4,
   3,1,5,-1,-1,-1,    2,3,0,2,5,3,     1,4,0,1,5,4,     4,2,5,-1,-1,-1,
   4,5,2,-1,-1,-1,    4,1,0,4,5,1,     3,2,0,3,5,2,     1,3,5,-1,-1,-1,
   4,1,2,4,3,1,       3,0,4,-1,-1,-1,  2,0,1,-1,-1,-1, -1,-1,-1,-1,-1,-1};
__device__ const signed char d_ea[6]   = {0,0,0,1,1,2};
__device__ const signed char d_eb[6]   = {1,2,3,2,3,3};
__device__ const signed char d_kuhn[24] = {0,1,3,7, 0,3,2,7, 0,2,6,7,
                                           0,6,4,7, 0,4,5,7, 0,5,1,7};

__device__ __forceinline__ int corner_off(int b) {
    return (b & 1) * ND2 + ((b >> 1) & 1) * NDIM + ((b >> 2) & 1);
}

// ---------------- warp-shuffle block scan (256 threads); loop-safe ----------------
template <typename T>
__device__ __forceinline__ T blockScanExcl256(T val, T& total) {
    unsigned lane = threadIdx.x & 31, w = threadIdx.x >> 5;
    T incl = val;
    #pragma unroll
    for (int o = 1; o < 32; o <<= 1) {
        T n = __shfl_up_sync(0xffffffffu, incl, o);
        if (lane >= o) incl += n;
    }
    __shared__ T ws[8];
    if (lane == 31) ws[w] = incl;
    __syncthreads();
    if (w == 0) {
        T x = (lane < 8) ? ws[lane] : T(0);
        #pragma unroll
        for (int o = 1; o < 8; o <<= 1) {
            T n = __shfl_up_sync(0xffffffffu, x, o);
            if (lane >= o) x += n;
        }
        if (lane < 8) ws[lane] = x;
    }
    __syncthreads();
    T base = (w > 0) ? ws[w - 1] : T(0);
    total = ws[7];
    __syncthreads();
    return base + incl - val;
}

// per-cube tet codes from occ byte: packed (lo16=#1tri, hi16=#2tri), fills ti6[]
__device__ __forceinline__ unsigned cube_codes(unsigned occ8, int* ti6) {
    const int ka[6] = {1,3,2,6,4,5};
    const int kb[6] = {3,2,6,4,5,1};
    unsigned sum = 0;
    #pragma unroll
    for (int ku = 0; ku < 6; ++ku) {
        int ti = (int)(occ8 & 1u)
               | (int)(((occ8 >> ka[ku]) & 1u) << 1)
               | (int)(((occ8 >> kb[ku]) & 1u) << 2)
               | (int)(((occ8 >> 7) & 1u) << 3);
        ti6[ku] = ti;
        int pc = __popc(ti);
        int nt = min(pc, 4 - pc);
        sum += (nt == 1) ? 1u : ((nt == 2) ? 0x10000u : 0u);
    }
    return sum;
}

// aligned smem->gmem copy: logical elem x lives at s[off+x]; (off & 3) == dst phase
__device__ __forceinline__ void copy_out(float* __restrict__ dst,
                                         const float* __restrict__ s,
                                         int off, int n, int tid) {
    int ph = (int)(((size_t)dst >> 2) & 3);
    int x0 = (4 - ph) & 3;
    if (x0 > n) x0 = n;
    if (tid < x0) dst[tid] = s[off + tid];
    int nv = (n - x0) >> 2;
    const float4* sv = (const float4*)(s + off + x0);
    float4* dv = (float4*)(dst + x0);
    for (int q = tid; q < nv; q += 256) dv[q] = sv[q];
    int done = x0 + (nv << 2);
    int rem = n - done;
    if (tid < rem) dst[done + tid] = s[off + done + tid];
}

// ================= kCount: masks + occ8 + tet counts + inline tail scan =================
__global__ void __launch_bounds__(256) kCount(const float* __restrict__ level,
                                              const int* __restrict__ thrp) {
    float thr = (float)thrp[0];
    if (blockIdx.x < NVB) {
        // ---- vertex branch ----
        int v = blockIdx.x * 256 + threadIdx.x;
        unsigned int mask = 0;
        if (v < NV) {
            int i = v / ND2;
            int r = v - i * ND2;
            int j = r / NDIM;
            int k = r - j * NDIM;
            bool oi = i < 64, oj = j < 64, ok = k < 64;
            bool o0 = (level[v] - thr) > 0.0f;
            #pragma unroll
            for (int d = 1; d < 8; ++d) {
                bool in = ((d & 4) ? oi : true) & ((d & 2) ? oj : true)
                        & ((d & 1) ? ok : true);
                if (in) {
                    int off = (d >> 2) * ND2 + ((d >> 1) & 1) * NDIM + (d & 1);
                    bool o1 = (level[v + off] - thr) > 0.0f;
                    if (o0 != o1) mask |= 1u << (d - 1);
                }
            }
        }
        int cnt = __popc(mask);
        int total;
        int excl = blockScanExcl256<int>(cnt, total);
        if (v < NV) g_pkl[v] = ((unsigned)excl << 7) | mask;
        if (threadIdx.x == 0) g_vblk[blockIdx.x] = total;
    } else {
        // ---- cube branch: classify 256 cubes straight from level, store occ8 ----
        int cb = blockIdx.x - NVB;
        int cube = cb * 256 + threadIdx.x;
        int ci = cube >> 12, cj = (cube >> 6) & 63, ck = cube & 63;
        int v000 = (ci * NDIM + cj) * NDIM + ck;
        unsigned occ8 = 0;
        #pragma unroll
        for (int b = 0; b < 8; ++b)
            occ8 |= ((level[v000 + corner_off(b)] - thr) > 0.0f ? 1u : 0u) << b;
        g_occ8[cube] = (unsigned char)occ8;
        int ti6[6];
        unsigned sum = cube_codes(occ8, ti6);

        // reduce per 128-cube half (matches kEmit face blocks)
        #pragma unroll
        for (int o = 16; o > 0; o >>= 1) sum += __shfl_down_sync(0xffffffffu, sum, o);
        __shared__ unsigned wsc[8];
        unsigned lane = threadIdx.x & 31, w = threadIdx.x >> 5;
        if (lane == 0) wsc[w] = sum;
        __syncthreads();
        if (threadIdx.x == 0) {
            unsigned tot = wsc[0] + wsc[1] + wsc[2] + wsc[3];
            g_tblk[2 * cb] = (unsigned long long)(tot & 0xFFFFu)
                           | ((unsigned long long)(tot >> 16) << 32);
        }
        if (threadIdx.x == 128) {
            unsigned tot = wsc[4] + wsc[5] + wsc[6] + wsc[7];
            g_tblk[2 * cb + 1] = (unsigned long long)(tot & 0xFFFFu)
                               | ((unsigned long long)(tot >> 16) << 32);
        }
    }

    // ---- last-block tail: both scans ----
    __shared__ unsigned s_ticket;
    if (threadIdx.x == 0) {
        __threadfence();
        s_ticket = atomicAdd(&g_done, 1u);
    }
    __syncthreads();
    if (s_ticket == NBLKC - 1) {
        __threadfence();

        int carry = 0;
        #pragma unroll
        for (int c = 0; c < 5; ++c) {          // 5*256 >= 1073
            int idx = c * 256 + threadIdx.x;
            int val = (idx < NVB) ? g_vblk[idx] : 0;
            int tot;
            int excl = blockScanExcl256<int>(val, tot);
            if (idx < NVB) g_vblk[idx] = excl + carry;
            carry += tot;
        }
        if (threadIdx.x == 0) { g_M = carry; g_vblk[NVB] = carry; }

        unsigned long long uc = 0;
        #pragma unroll
        for (int c = 0; c < 8; ++c) {          // 8*256 == 2048
            int idx = c * 256 + threadIdx.x;
            unsigned long long val = g_tblk[idx];
            unsigned long long tot;
            unsigned long long excl = blockScanExcl256<unsigned long long>(val, tot);
            g_tblk[idx] = excl + uc;
            uc += tot;
        }
        if (threadIdx.x == 0) {
            g_F1 = (int)(uc & 0xFFFFFFFFull);
            __threadfence();
            g_done = 0;
        }
    }
}

// ================= kEmit: fused verts + faces =================
__global__ void __launch_bounds__(256, 6)
kEmit(const float* __restrict__ level, const int* __restrict__ thrp,
      float* __restrict__ out) {
    __shared__ __align__(16) float s_raw[5408];   // verts staging / face staging
    __shared__ unsigned       s_pack[390];        // dedup corner cache
    __shared__ unsigned short s_ptab[768];        // (ku,ti) -> 6 packed edges
    __shared__ unsigned short s_desc[1536];       // face descriptors

    int tid = threadIdx.x;
    if (blockIdx.x < NVB) {
        // ---- emit vertices ----
        int v = blockIdx.x * 256 + tid;
        unsigned pk = (v < NV) ? g_pkl[v] : 0u;
        unsigned mask = pk & 0x7Fu;
        int excl = (int)(pk >> 7);
        int gbase = g_vblk[blockIdx.x];
        int total = g_vblk[blockIdx.x + 1] - gbase;
        int pad = (3 * gbase) & 3;                 // dst element phase

        if (mask) {
            float thr = (float)thrp[0];
            const float inv = 1.0f / 64.0f;
            int i = v / ND2;
            int r = v - i * ND2;
            int j = r / NDIM;
            int k = r - j * NDIM;
            float s0  = level[v] - thr;
            float p0x = (float)i * inv, p0y = (float)j * inv, p0z = (float)k * inv;
            int sp = pad + excl * 3;
            #pragma unroll
            for (int d = 1; d < 8; ++d) {
                if (mask & (1u << (d - 1))) {
                    int di = d >> 2, dj = (d >> 1) & 1, dk = d & 1;
                    int w = v + di * ND2 + dj * NDIM + dk;
                    float s1 = level[w] - thr;
                    float rdenom = 1.0f / (s0 - s1);
                    float w0 = (-s1) * rdenom;
                    float w1 = s0 * rdenom;
                    s_raw[sp + 0] = p0x * w0 + (float)(i + di) * inv * w1;
                    s_raw[sp + 1] = p0y * w0 + (float)(j + dj) * inv * w1;
                    s_raw[sp + 2] = p0z * w0 + (float)(k + dk) * inv * w1;
                    sp += 3;
                }
            }
        }
        __syncthreads();
        copy_out(out + 3ll * gbase, s_raw, pad, 3 * total, tid);
    } else {
        // ---- emit faces ----
        int cb = blockIdx.x - NVB;
        int cbase = cb * CPB;
        int ci = cbase >> 12, cj0 = (cbase >> 6) & 63;

        // build fused edge table: (ku,ti) -> up to 6 packed edges, pure ALU
        if (tid < 96) {
            int ku = tid >> 4, ti = tid & 15;
            #pragma unroll
            for (int s = 0; s < 6; ++s) {
                int le = d_tri[ti * 6 + s];
                unsigned short pv = 0;
                if (le >= 0) {
                    int ba = d_kuhn[ku * 4 + d_ea[le]];
                    int bb = d_kuhn[ku * 4 + d_eb[le]];
                    int lo = ba & bb;
                    int dd = ba ^ bb;
                    int li = lo & 1, lj = (lo >> 1) & 1, lk = (lo >> 2) & 1;
                    int bit = (((dd & 1) << 2) | (dd & 2) | ((dd >> 2) & 1)) - 1;
                    pv = (unsigned short)((((li * 3 + lj) * 65 + lk) << 3) | bit);
                }
                s_ptab[tid * 8 + s] = pv;
            }
        }

        // classify own cube (tid < 128) from occ8 byte
        int ti6[6];
        unsigned sum = 0;
        if (tid < CPB)
            sum = cube_codes((unsigned)g_occ8[cbase + tid], ti6);

        unsigned total;
        unsigned run = blockScanExcl256<unsigned>(sum, total);  // syncs cover s_ptab
        int T1 = (int)(total & 0xFFFFu);
        int T2 = (int)(total >> 16);

        // global bases & staging offsets with alignment phases
        unsigned long long blk = g_tblk[cb];
        int c1base = (int)(blk & 0xFFFFFFFFull);
        int c2base = (int)(blk >> 32);
        int M = g_M, F1 = g_F1;
        int ph1 = (3 * (M + c1base)) & 3;
        int ph2 = (3 * (M + F1 + 2 * c2base)) & 3;
        int o1 = ph1;
        int o2 = ((o1 + 3 * T1 + 3) & ~3) + ph2;

        // write descriptors in final face order
        if (tid < CPB) {
            int c1 = (int)(run & 0xFFFFu);
            int c2 = (int)(run >> 16);
            #pragma unroll
            for (int ku = 0; ku < 6; ++ku) {
                int ti = ti6[ku];
                int pc = __popc(ti);
                int nt = min(pc, 4 - pc);
                if (nt == 1) {
                    s_desc[c1++] = (unsigned short)(tid | (ku << 7) | (ti << 11));
                } else if (nt == 2) {
                    int s = T1 + 2 * c2;
                    s_desc[s]     = (unsigned short)(tid | (ku << 7) | (ti << 11));
                    s_desc[s + 1] = (unsigned short)(tid | (ku << 7) | (1 << 10) | (ti << 11));
                    c2++;
                }
            }
        }

        // dedup corner cache: 390 distinct vertices (2 i x 3 j x 65 k)
        for (int idx = tid; idx < 390; idx += 256) {
            int rrow = idx / 65;
            int kk   = idx - rrow * 65;
            int li   = (rrow >= 3) ? 1 : 0;
            int ljj  = rrow - 3 * li;
            int vc = ((ci + li) * NDIM + (cj0 + ljj)) * NDIM + kk;
            unsigned pk = g_pkl[vc];
            s_pack[idx] = (((unsigned)g_vblk[vc >> 8] + (pk >> 7)) << 7) | (pk & 0x7Fu);
        }
        __syncthreads();

        // uniform loop over compacted faces
        int nfaces = T1 + 2 * T2;
        for (int f = tid; f < nfaces; f += 256) {
            unsigned d = s_desc[f];
            int cube_l = d & 127;
            int ku  = (d >> 7) & 7;
            int tri = (d >> 10) & 1;
            int ti  = d >> 11;
            int vmoff = cube_l + (cube_l >> 6);    // jrow*65 + ck
            int sp = (f < T1) ? (o1 + 3 * f) : (o2 + 3 * (f - T1));
            const unsigned short* pt = &s_ptab[(ku * 16 + ti) * 8 + 3 * tri];
            #pragma unroll
            for (int e = 0; e < 3; ++e) {
                unsigned pe = pt[e];
                unsigned pk = s_pack[(pe >> 3) + vmoff];
                int vidx = (int)(pk >> 7) + __popc(pk & ((1u << (pe & 7)) - 1u));
                s_raw[sp + e] = (float)vidx;
            }
        }
        __syncthreads();

        // two coalesced, vectorized copy-outs
        float* fout = out + 3ll * M;
        copy_out(fout + 3ll * c1base, s_raw, o1, 3 * T1, tid);
        copy_out(fout + 3ll * (F1 + 2ll * c2base), s_raw, o2, 6 * T2, tid);
    }
}

// ---------------- launch ----------------
extern "C" void kernel_launch(void* const* d_in, const int* in_sizes, int n_in,
                              void* d_out, int out_size) {
    const float* level = (const float*)d_in[0];
    const int*   thrp  = (const int*)d_in[3];
    float*       out   = (float*)d_out;
    (void)in_sizes; (void)n_in; (void)out_size;

    kCount<<<NBLKC, 256>>>(level, thrp);
    kEmit <<<NBLKE, 256>>>(level, thrp, out);
}

// round 10
// speedup vs baseline: 1.1837x; 1.1837x over previous
#include <cuda_runtime.h>

#define NDIM 65
#define ND2  4225
#define NV   274625
#define NVB  1073            /* 256-vertex blocks            */
#define NC   262144          /* 64^3 cubes                   */
#define NCB  1024            /* cube blocks of 256           */
#define NBLK (NVB + NCB)     /* 2097 blocks in fused kernels */

// -------- scratch (device globals; no allocations allowed) --------
__device__ unsigned int       g_pkl[NV];      // (block-local excl << 7) | mask
__device__ int                g_vblk[NVB+1];  // block totals -> scanned bases (+M)
__device__ unsigned char      g_occ8[NC];     // per-cube 8-bit occupancy
__device__ unsigned long long g_tblk[NCB];    // lo32=c1 base, hi32=c2 base
__device__ int                g_M;
__device__ int                g_F1;

__device__ const signed char d_tri[96] = {
  -1,-1,-1,-1,-1,-1,  1,0,2,-1,-1,-1,  4,0,3,-1,-1,-1,  1,4,2,1,3,4,
   3,1,5,-1,-1,-1,    2,3,0,2,5,3,     1,4,0,1,5,4,     4,2,5,-1,-1,-1,
   4,5,2,-1,-1,-1,    4,1,0,4,5,1,     3,2,0,3,5,2,     1,3,5,-1,-1,-1,
   4,1,2,4,3,1,       3,0,4,-1,-1,-1,  2,0,1,-1,-1,-1, -1,-1,-1,-1,-1,-1};
__device__ const signed char d_ea[6]   = {0,0,0,1,1,2};
__device__ const signed char d_eb[6]   = {1,2,3,2,3,3};
__device__ const signed char d_kuhn[24] = {0,1,3,7, 0,3,2,7, 0,2,6,7,
                                           0,6,4,7, 0,4,5,7, 0,5,1,7};

__device__ __forceinline__ int corner_off(int b) {
    return (b & 1) * ND2 + ((b >> 1) & 1) * NDIM + ((b >> 2) & 1);
}

// ---------------- warp-shuffle block scan (256 threads) ----------------
template <typename T>
__device__ __forceinline__ T blockScanExcl256(T val, T& total) {
    unsigned lane = threadIdx.x & 31, w = threadIdx.x >> 5;
    T incl = val;
    #pragma unroll
    for (int o = 1; o < 32; o <<= 1) {
        T n = __shfl_up_sync(0xffffffffu, incl, o);
        if (lane >= o) incl += n;
    }
    __shared__ T ws[8];
    if (lane == 31) ws[w] = incl;
    __syncthreads();
    if (w == 0) {
        T x = (lane < 8) ? ws[lane] : T(0);
        #pragma unroll
        for (int o = 1; o < 8; o <<= 1) {
            T n = __shfl_up_sync(0xffffffffu, x, o);
            if (lane >= o) x += n;
        }
        if (lane < 8) ws[lane] = x;
    }
    __syncthreads();
    T base = (w > 0) ? ws[w - 1] : T(0);
    total = ws[7];
    return base + incl - val;
}

// per-cube tet codes from occ byte: packed (lo16=#1tri, hi16=#2tri), fills ti6[]
__device__ __forceinline__ unsigned cube_codes(unsigned occ8, int* ti6) {
    const int ka[6] = {1,3,2,6,4,5};
    const int kb[6] = {3,2,6,4,5,1};
    unsigned sum = 0;
    #pragma unroll
    for (int ku = 0; ku < 6; ++ku) {
        int ti = (int)(occ8 & 1u)
               | (int)(((occ8 >> ka[ku]) & 1u) << 1)
               | (int)(((occ8 >> kb[ku]) & 1u) << 2)
               | (int)(((occ8 >> 7) & 1u) << 3);
        ti6[ku] = ti;
        int pc = __popc(ti);
        int nt = min(pc, 4 - pc);
        sum += (nt == 1) ? 1u : ((nt == 2) ? 0x10000u : 0u);
    }
    return sum;
}

// ================= kCount: fused vertex masks + tet class counts =================
__global__ void kCount(const float* __restrict__ level, const int* __restrict__ thrp) {
    float thr = (float)thrp[0];
    if (blockIdx.x < NVB) {
        // ---- vertex branch ----
        int v = blockIdx.x * 256 + threadIdx.x;
        unsigned int mask = 0;
        if (v < NV) {
            int i = v / ND2;
            int r = v - i * ND2;
            int j = r / NDIM;
            int k = r - j * NDIM;
            bool o0 = (level[v] - thr) > 0.0f;
            #pragma unroll
            for (int d = 1; d < 8; ++d) {
                int di = d >> 2, dj = (d >> 1) & 1, dk = d & 1;
                if (i + di < NDIM && j + dj < NDIM && k + dk < NDIM) {
                    bool o1 = (level[v + di * ND2 + dj * NDIM + dk] - thr) > 0.0f;
                    if (o0 != o1) mask |= 1u << (d - 1);
                }
            }
        }
        int cnt = __popc(mask);
        int total;
        int excl = blockScanExcl256<int>(cnt, total);
        if (v < NV) g_pkl[v] = ((unsigned)excl << 7) | mask;
        if (threadIdx.x == 0) g_vblk[blockIdx.x] = total;
    } else {
        // ---- cube branch: classify tets straight from level, store occ8 ----
        int cb = blockIdx.x - NVB;
        int cube = cb * 256 + threadIdx.x;
        int ci = cube >> 12, cj = (cube >> 6) & 63, ck = cube & 63;
        int v000 = (ci * NDIM + cj) * NDIM + ck;
        unsigned occ8 = 0;
        #pragma unroll
        for (int b = 0; b < 8; ++b)
            occ8 |= ((level[v000 + corner_off(b)] - thr) > 0.0f ? 1u : 0u) << b;
        g_occ8[cube] = (unsigned char)occ8;
        int ti6[6];
        unsigned sum = cube_codes(occ8, ti6);

        #pragma unroll
        for (int o = 16; o > 0; o >>= 1) sum += __shfl_down_sync(0xffffffffu, sum, o);
        __shared__ unsigned ws[8];
        unsigned lane = threadIdx.x & 31, w = threadIdx.x >> 5;
        if (lane == 0) ws[w] = sum;
        __syncthreads();
        if (threadIdx.x == 0) {
            unsigned tot = 0;
            #pragma unroll
            for (int x = 0; x < 8; ++x) tot += ws[x];
            g_tblk[cb] = (unsigned long long)(tot & 0xFFFFu)
                       | ((unsigned long long)(tot >> 16) << 32);
        }
    }
}

// ================= kScan: both small scans =================
__global__ void kScan() {
    int t = threadIdx.x;
    unsigned lane = t & 31, w = t >> 5;

    { // vertex block bases (1073 ints, 2/thread)
        int i0 = 2 * t, i1 = 2 * t + 1;
        int e0 = (i0 < NVB) ? g_vblk[i0] : 0;
        int e1 = (i1 < NVB) ? g_vblk[i1] : 0;
        int val = e0 + e1;
        int incl = val;
        #pragma unroll
        for (int o = 1; o < 32; o <<= 1) {
            int n = __shfl_up_sync(0xffffffffu, incl, o);
            if (lane >= o) incl += n;
        }
        __shared__ int wsA[32];
        if (lane == 31) wsA[w] = incl;
        __syncthreads();
        if (w == 0) {
            int x = wsA[lane];
            #pragma unroll
            for (int o = 1; o < 32; o <<= 1) {
                int n = __shfl_up_sync(0xffffffffu, x, o);
                if (lane >= o) x += n;
            }
            wsA[lane] = x;
        }
        __syncthreads();
        int excl = ((w > 0) ? wsA[w - 1] : 0) + incl - val;
        if (i0 < NVB) g_vblk[i0] = excl;
        if (i1 < NVB) g_vblk[i1] = excl + e0;
        if (t == 1023) { g_M = excl + val; g_vblk[NVB] = excl + val; }
        __syncthreads();
    }

    { // tet block bases (1024 u64)
        unsigned long long val = g_tblk[t];
        unsigned long long incl = val;
        #pragma unroll
        for (int o = 1; o < 32; o <<= 1) {
            unsigned long long n = __shfl_up_sync(0xffffffffu, incl, o);
            if (lane >= o) incl += n;
        }
        __shared__ unsigned long long wsB[32];
        if (lane == 31) wsB[w] = incl;
        __syncthreads();
        if (w == 0) {
            unsigned long long x = wsB[lane];
            #pragma unroll
            for (int o = 1; o < 32; o <<= 1) {
                unsigned long long n = __shfl_up_sync(0xffffffffu, x, o);
                if (lane >= o) x += n;
            }
            wsB[lane] = x;
        }
        __syncthreads();
        unsigned long long excl = ((w > 0) ? wsB[w - 1] : 0ull) + incl - val;
        g_tblk[t] = excl;
        if (t == 1023) g_F1 = (int)((excl + val) & 0xFFFFFFFFull);
    }
}

// ================= kEmit: fused verts + faces =================
__global__ void kEmit(const float* __restrict__ level, const int* __restrict__ thrp,
                      float* __restrict__ out) {
    __shared__ float    s_stage[9216];       // 36 KB: verts (<=5376) or faces (<=9216)
    __shared__ unsigned s_pack[8 * 256];     // face-branch corner cache
    __shared__ int      s_tri[96];
    __shared__ int      s_edge[36];

    if (blockIdx.x < NVB) {
        // ---- emit vertices ----
        int v = blockIdx.x * 256 + threadIdx.x;
        unsigned pk = (v < NV) ? g_pkl[v] : 0u;
        unsigned mask = pk & 0x7Fu;
        int excl = (int)(pk >> 7);
        int gbase = g_vblk[blockIdx.x];
        int total = g_vblk[blockIdx.x + 1] - gbase;

        if (mask) {
            float thr = (float)thrp[0];
            const float inv = 1.0f / 64.0f;
            int i = v / ND2;
            int r = v - i * ND2;
            int j = r / NDIM;
            int k = r - j * NDIM;
            float s0  = level[v] - thr;
            float p0x = (float)i * inv, p0y = (float)j * inv, p0z = (float)k * inv;
            int sp = excl * 3;
            #pragma unroll
            for (int d = 1; d < 8; ++d) {
                if (mask & (1u << (d - 1))) {
                    int di = d >> 2, dj = (d >> 1) & 1, dk = d & 1;
                    int w = v + di * ND2 + dj * NDIM + dk;
                    float s1 = level[w] - thr;
                    float rdenom = 1.0f / (s0 - s1);
                    float w0 = (-s1) * rdenom;
                    float w1 = s0 * rdenom;
                    s_stage[sp + 0] = p0x * w0 + (float)(i + di) * inv * w1;
                    s_stage[sp + 1] = p0y * w0 + (float)(j + dj) * inv * w1;
                    s_stage[sp + 2] = p0z * w0 + (float)(k + dk) * inv * w1;
                    sp += 3;
                }
            }
        }
        __syncthreads();
        float* dst = out + 3ll * gbase;
        int n = 3 * total;
        for (int x = threadIdx.x; x < n; x += 256) dst[x] = s_stage[x];
    } else {
        // ---- emit faces ----
        int tid = threadIdx.x;
        if (tid < 96) s_tri[tid] = d_tri[tid];
        if (tid < 36) {
            int ku = tid / 6, le = tid - ku * 6;
            int ba = d_kuhn[ku * 4 + d_ea[le]];
            int bb = d_kuhn[ku * 4 + d_eb[le]];
            int lo = ba & bb;
            int dd = ba ^ bb;
            int bit = (((dd & 1) << 2) | (dd & 2) | ((dd >> 2) & 1)) - 1;
            s_edge[tid] = (lo << 3) | bit;
        }

        int cb = blockIdx.x - NVB;
        int cube = cb * 256 + tid;
        int ci = cube >> 12, cj = (cube >> 6) & 63, ck = cube & 63;
        int v000 = (ci * NDIM + cj) * NDIM + ck;
        unsigned occ8 = (unsigned)g_occ8[cube];      // 1 byte load, coalesced
        int ti6[6];
        unsigned sum = cube_codes(occ8, ti6);

        // corner cache with global vertex base folded in
        #pragma unroll
        for (int c = 0; c < 8; ++c) {
            int vc = v000 + corner_off(c);
            unsigned pk = g_pkl[vc];
            s_pack[c * 256 + tid] =
                (((unsigned)g_vblk[vc >> 8] + (pk >> 7)) << 7) | (pk & 0x7Fu);
        }

        unsigned total;
        unsigned run = blockScanExcl256<unsigned>(sum, total);  // syncs cover s_* writes
        int total1 = (int)(total & 0xFFFFu);
        int total2 = (int)(total >> 16);

        // build faces into smem at block-local offsets
        #pragma unroll
        for (int ku = 0; ku < 6; ++ku) {
            int ti = ti6[ku];
            int pc = __popc(ti);
            int nt = min(pc, 4 - pc);
            if (nt == 0) continue;
            int sp;
            unsigned code;
            if (nt == 1) { sp = 3 * (int)(run & 0xFFFFu);           code = 1u; }
            else         { sp = 3 * total1 + 6 * (int)(run >> 16);  code = 0x10000u; }
            int nent = 3 * nt;
            for (int e = 0; e < nent; ++e) {
                int le = s_tri[ti * 6 + e];
                int pe = s_edge[ku * 6 + le];
                unsigned pk = s_pack[(pe >> 3) * 256 + tid];
                unsigned bit = (unsigned)(pe & 7);
                int vidx = (int)(pk >> 7) + __popc(pk & 0x7Fu & ((1u << bit) - 1u));
                s_stage[sp + e] = (float)vidx;
            }
            run += code;
        }
        __syncthreads();

        unsigned long long blk = g_tblk[cb];
        int c1base = (int)(blk & 0xFFFFFFFFull);
        int c2base = (int)(blk >> 32);
        float* fout = out + 3ll * g_M;

        float* dst1 = fout + 3ll * c1base;
        int n1 = 3 * total1;
        for (int x = tid; x < n1; x += 256) dst1[x] = s_stage[x];
        float* dst2 = fout + 3ll * (g_F1 + 2ll * c2base);
        int n2 = 6 * total2;
        const float* src2 = s_stage + n1;
        for (int x = tid; x < n2; x += 256) dst2[x] = src2[x];
    }
}

// ---------------- launch ----------------
extern "C" void kernel_launch(void* const* d_in, const int* in_sizes, int n_in,
                              void* d_out, int out_size) {
    const float* level = (const float*)d_in[0];
    const int*   thrp  = (const int*)d_in[3];
    float*       out   = (float*)d_out;
    (void)in_sizes; (void)n_in; (void)out_size;

    kCount<<<NBLK, 256>>>(level, thrp);
    kScan <<<1, 1024>>>();
    kEmit <<<NBLK, 256>>>(level, thrp, out);
}